// round 2
// baseline (speedup 1.0000x reference)
#include <cuda_runtime.h>
#include <stdint.h>

// Problem constants (fixed by the reference).
#define MM      512      // checks
#define NN      1024     // variables
#define EE      3072     // edges
#define NITERS  10
#define WB      4        // batch elements per CTA (float4 lanes)
#define THREADS 512

#define LOG2E 1.4426950408889634f
#define LN2   0.6931471805599453f
#define CLIP  0.999995f

// ---------------- device-global scratch (no runtime allocation) --------------
// Per-iteration packed edge meta: {i0_slot | i1_slot<<16, lwslot(var) | swz(e)<<16, w0, w1}
__device__ __align__(16) uint4 g_ph1[NITERS * EE];     // 480 KB
__device__ float g_lw[NITERS * NN];                    // llr_iter * log2e
__device__ uint2  g_finidx[MM];                        // swizzled final edge slots
__device__ float4 g_finw[MM];                          // {wf0*ln2, wf1*ln2, wf2*ln2, llr_final}

// rotation swizzle within each check's 6-slot block (breaks stride-24-word conflicts)
__device__ __forceinline__ int swz(int e) {
    int r = e / 6; int j = e - r * 6;
    int k = j + (r % 6); if (k >= 6) k -= 6;
    return r * 6 + k;
}
// index-expansion swizzle for the llr*lw table (stride-2 var gathers -> conflict-free)
__device__ __forceinline__ int lwslot(int v) { return v + (v >> 3); }
#define LW_SLOTS 1152   // max lwslot(1023) = 1150, padded

// ---------------------------------- prep -------------------------------------
__global__ void prep_kernel(const float* __restrict__ w_iter,
                            const float* __restrict__ llr_iter,
                            const float* __restrict__ w_final,
                            const float* __restrict__ llr_final,
                            const int*   __restrict__ v_sum,
                            const int*   __restrict__ edge_var,
                            const int*   __restrict__ fin_idx) {
    int t = blockIdx.x * blockDim.x + threadIdx.x;
    if (t < NITERS * EE) {
        int e = t % EE;
        int i0 = swz(v_sum[2 * e]);
        int i1 = swz(v_sum[2 * e + 1]);
        int vs = lwslot(edge_var[e]);
        uint4 p;
        p.x = (unsigned)i0 | ((unsigned)i1 << 16);
        p.y = (unsigned)vs | ((unsigned)swz(e) << 16);
        p.z = __float_as_uint(w_iter[2 * t]);       // w_iter[it][2e]
        p.w = __float_as_uint(w_iter[2 * t + 1]);   // w_iter[it][2e+1]
        g_ph1[t] = p;
    }
    if (t < NITERS * NN) g_lw[t] = llr_iter[t] * LOG2E;
    if (t < MM) {
        int a = swz(fin_idx[3 * t]);
        int b = swz(fin_idx[3 * t + 1]);
        int c = swz(fin_idx[3 * t + 2]);
        g_finidx[t] = make_uint2((unsigned)a | ((unsigned)b << 16), (unsigned)c);
        g_finw[t]   = make_float4(w_final[3 * t] * LN2, w_final[3 * t + 1] * LN2,
                                  w_final[3 * t + 2] * LN2, llr_final[t]);
    }
}

// ------------------------------- fast math -----------------------------------
__device__ __forceinline__ float ex2f_(float x) { float y; asm("ex2.approx.f32 %0, %1;" : "=f"(y) : "f"(x)); return y; }
__device__ __forceinline__ float lg2f_(float x) { float y; asm("lg2.approx.f32 %0, %1;" : "=f"(y) : "f"(x)); return y; }
__device__ __forceinline__ float rcpf_(float x) { float y; asm("rcp.approx.f32 %0, %1;" : "=f"(y) : "f"(x)); return y; }

// v2c = tanh(0.5 * x_natural); u = x * log2e  ->  (2^u - 1)/(2^u + 1)
__device__ __forceinline__ float vmsg(float a, float b, float L, float w0, float w1) {
    float u = fmaf(a, w0, fmaf(b, w1, L));
    float E = ex2f_(u);
    float r = rcpf_(E + 1.0f);
    return fmaf(-2.0f, r, 1.0f);
}
// c2v (log2-scaled): lg2((1+t)/(1-t)); ln2 is folded into consumer weights
__device__ __forceinline__ float cmsg(float p) {
    float t = p * CLIP;
    return lg2f_(1.0f + t) - lg2f_(1.0f - t);
}
__device__ __forceinline__ float4 mul4(float4 a, float4 b) {
    return make_float4(a.x * b.x, a.y * b.y, a.z * b.z, a.w * b.w);
}
__device__ __forceinline__ float4 cmsg4(float4 p) {
    return make_float4(cmsg(p.x), cmsg(p.y), cmsg(p.z), cmsg(p.w));
}

// --------------------------------- main --------------------------------------
extern __shared__ float4 s_dyn[];

__global__ void __launch_bounds__(THREADS, 2)
bp_kernel(const float* __restrict__ llr, float* __restrict__ out) {
    float4* s_c2v = s_dyn;           // EE float4  (48 KB), rotation-swizzled slots
    float4* s_lw  = s_dyn + EE;      // LW_SLOTS float4 (18 KB), index-expanded
    const int tid = threadIdx.x;
    const long b0 = (long)blockIdx.x * WB;
    const float* llr0 = llr + b0 * NN;

    // zero c2v (iteration 0 reads zeros)
#pragma unroll
    for (int k = 0; k < EE / THREADS; k++)
        s_c2v[tid + k * THREADS] = make_float4(0.f, 0.f, 0.f, 0.f);

    int ro = tid % 6;   // this thread's store rotation

    for (int it = 0; it < NITERS; it++) {
        // stage llr * (llr_iter * log2e) for this iteration, all 4 batch lanes
#pragma unroll
        for (int k = 0; k < NN / THREADS; k++) {
            int v = tid + k * THREADS;
            float lw = g_lw[it * NN + v];
            float4 L;
            L.x = llr0[v]          * lw;
            L.y = llr0[NN + v]     * lw;
            L.z = llr0[2 * NN + v] * lw;
            L.w = llr0[3 * NN + v] * lw;
            s_lw[lwslot(v)] = L;
        }
        __syncthreads();

        // fused variable->check + check->variable for check r = tid
        float4 O[6];
        {
            float4 V[6];
            const uint4* meta = g_ph1 + it * EE + tid * 6;
#pragma unroll
            for (int j = 0; j < 6; j++) {
                uint4 m = meta[j];
                float4 A  = s_c2v[m.x & 0xFFFFu];
                float4 Bv = s_c2v[m.x >> 16];
                float4 L  = s_lw [m.y & 0xFFFFu];
                float w0 = __uint_as_float(m.z);
                float w1 = __uint_as_float(m.w);
                V[j].x = vmsg(A.x, Bv.x, L.x, w0, w1);
                V[j].y = vmsg(A.y, Bv.y, L.y, w0, w1);
                V[j].z = vmsg(A.z, Bv.z, L.z, w0, w1);
                V[j].w = vmsg(A.w, Bv.w, L.w, w0, w1);
            }
            // extrinsic products via prefix/suffix
            float4 s5 = V[5];
            float4 s4 = mul4(V[4], s5);
            float4 s3 = mul4(V[3], s4);
            float4 s2 = mul4(V[2], s3);
            float4 s1 = mul4(V[1], s2);
            O[0] = cmsg4(s1);
            float4 pre = V[0];
            O[1] = cmsg4(mul4(pre, s2)); pre = mul4(pre, V[1]);
            O[2] = cmsg4(mul4(pre, s3)); pre = mul4(pre, V[2]);
            O[3] = cmsg4(mul4(pre, s4)); pre = mul4(pre, V[3]);
            O[4] = cmsg4(mul4(pre, s5)); pre = mul4(pre, V[4]);
            O[5] = cmsg4(pre);
        }
        __syncthreads();   // everyone done reading old c2v before overwrite

        float4* dst = s_c2v + tid * 6;
#pragma unroll
        for (int j = 0; j < 6; j++) {
            int slot = j + ro; if (slot >= 6) slot -= 6;
            dst[slot] = O[j];
        }
    }
    __syncthreads();

    // final marginalization for variable v = tid (only first N-M = 512 output)
    uint2 fi = g_finidx[tid];
    float4 fw = g_finw[tid];
    float4 A  = s_c2v[fi.x & 0xFFFFu];
    float4 Bv = s_c2v[fi.x >> 16];
    float4 C  = s_c2v[fi.y];
    float l0 = llr0[tid], l1 = llr0[NN + tid], l2 = llr0[2 * NN + tid], l3 = llr0[3 * NN + tid];
    float4 o;
    o.x = fmaf(A.x, fw.x, fmaf(Bv.x, fw.y, fmaf(C.x, fw.z, l0 * fw.w)));
    o.y = fmaf(A.y, fw.x, fmaf(Bv.y, fw.y, fmaf(C.y, fw.z, l1 * fw.w)));
    o.z = fmaf(A.z, fw.x, fmaf(Bv.z, fw.y, fmaf(C.z, fw.z, l2 * fw.w)));
    o.w = fmaf(A.w, fw.x, fmaf(Bv.w, fw.y, fmaf(C.w, fw.z, l3 * fw.w)));
    float4 s;
    s.x = rcpf_(1.0f + ex2f_(-o.x * LOG2E));
    s.y = rcpf_(1.0f + ex2f_(-o.y * LOG2E));
    s.z = rcpf_(1.0f + ex2f_(-o.z * LOG2E));
    s.w = rcpf_(1.0f + ex2f_(-o.w * LOG2E));
    out[(b0 + 0) * MM + tid] = s.x;
    out[(b0 + 1) * MM + tid] = s.y;
    out[(b0 + 2) * MM + tid] = s.z;
    out[(b0 + 3) * MM + tid] = s.w;
}

// ------------------------------ launch ---------------------------------------
extern "C" void kernel_launch(void* const* d_in, const int* in_sizes, int n_in,
                              void* d_out, int out_size) {
    const float* llr       = (const float*)d_in[0];
    const float* w_iter    = (const float*)d_in[1];
    const float* llr_iter  = (const float*)d_in[2];
    const float* w_final   = (const float*)d_in[3];
    const float* llr_final = (const float*)d_in[4];
    const int*   v_sum     = (const int*)d_in[5];
    // d_in[6] = c_prod_idx: redundant (check r owns edges 6r..6r+5 contiguously)
    const int*   edge_var  = (const int*)d_in[7];
    const int*   fin_idx   = (const int*)d_in[8];

    int B = in_sizes[0] / NN;                 // 8192
    size_t smem = (size_t)(EE + LW_SLOTS) * sizeof(float4);   // 67.5 KB

    cudaFuncSetAttribute(bp_kernel, cudaFuncAttributeMaxDynamicSharedMemorySize, (int)smem);

    prep_kernel<<<(NITERS * EE + 255) / 256, 256>>>(w_iter, llr_iter, w_final, llr_final,
                                                    v_sum, edge_var, fin_idx);
    bp_kernel<<<B / WB, THREADS, smem>>>(llr, (float*)d_out);
}

// round 3
// speedup vs baseline: 1.2710x; 1.2710x over previous
#include <cuda_runtime.h>
#include <stdint.h>

// Problem constants (fixed by the reference).
#define MM      512      // checks
#define NN      1024     // variables
#define EE      3072     // edges
#define NITERS  10
#define THREADS 512
#define CSTRIDE 7                 // float4 slots per check (112B -> conflict-free)
#define CSLOTS  (MM * CSTRIDE)    // 3584 float4
#define LW_SLOTS 1152             // llr table with v + (v>>3) expansion

#define LOG2E 1.4426950408889634f
#define LN2   0.6931471805599453f
#define CLIP  0.999995f
#define UCLAMP 24.0f              // |log2 e^x| clamp: t within 1.2e-7 of true, products <= 2^121

// ---------------- device-global scratch (no runtime allocation) --------------
// Per-iteration packed edge meta: {i0_slot | i1_slot<<16, w0, w1, lw*log2e}
__device__ __align__(16) uint4 g_meta[NITERS * EE];       // 480 KB
__device__ unsigned short g_vslot[EE];                    // llr-table slot of each edge's variable
__device__ uint2  g_finidx[MM];                           // padded final edge slots
__device__ float4 g_finw[MM];                             // {wf0*ln2, wf1*ln2, wf2*ln2, llr_final}

__device__ __forceinline__ int slot7(int e) { return (e / 6) * CSTRIDE + (e % 6); }
__device__ __forceinline__ int lwslot(int v) { return v + (v >> 3); }

// ---------------------------------- prep -------------------------------------
__global__ void prep_kernel(const float* __restrict__ w_iter,
                            const float* __restrict__ llr_iter,
                            const float* __restrict__ w_final,
                            const float* __restrict__ llr_final,
                            const int*   __restrict__ v_sum,
                            const int*   __restrict__ edge_var,
                            const int*   __restrict__ fin_idx) {
    int t = blockIdx.x * blockDim.x + threadIdx.x;
    if (t < NITERS * EE) {
        int e = t % EE;
        uint4 p;
        p.x = (unsigned)slot7(v_sum[2 * e]) | ((unsigned)slot7(v_sum[2 * e + 1]) << 16);
        p.y = __float_as_uint(w_iter[2 * t]);                       // w_iter[it][2e]
        p.z = __float_as_uint(w_iter[2 * t + 1]);                   // w_iter[it][2e+1]
        p.w = __float_as_uint(llr_iter[(t / EE) * NN + edge_var[e]] * LOG2E);
        g_meta[t] = p;
    }
    if (t < EE) g_vslot[t] = (unsigned short)lwslot(edge_var[t]);
    if (t < MM) {
        g_finidx[t] = make_uint2((unsigned)slot7(fin_idx[3 * t]) |
                                 ((unsigned)slot7(fin_idx[3 * t + 1]) << 16),
                                 (unsigned)slot7(fin_idx[3 * t + 2]));
        g_finw[t] = make_float4(w_final[3 * t] * LN2, w_final[3 * t + 1] * LN2,
                                w_final[3 * t + 2] * LN2, llr_final[t]);
    }
}

// ------------------------------- fast math -----------------------------------
__device__ __forceinline__ float ex2f_(float x) { float y; asm("ex2.approx.f32 %0, %1;" : "=f"(y) : "f"(x)); return y; }
__device__ __forceinline__ float lg2f_(float x) { float y; asm("lg2.approx.f32 %0, %1;" : "=f"(y) : "f"(x)); return y; }
__device__ __forceinline__ float rcpf_(float x) { float y; asm("rcp.approx.f32 %0, %1;" : "=f"(y) : "f"(x)); return y; }

// Check node for one 2-lane pair. E[j] = e^{x_j} (as 2^u). Emits per-edge
// extrinsic log2-domain messages directly to shared (dst[2*j], stride-2 float2).
//   t_ext,k = prod_{j!=k} (E_j-1)/(E_j+1) = A_k / B_k
//   msg_k   = lg2(B_k + CLIP*A_k) - lg2(B_k - CLIP*A_k)
__device__ __forceinline__ void check_pair(const float2* __restrict__ E,
                                           float2* __restrict__ dst) {
    float2 SP[6], SM[6];                 // suffix products of (E+1), (E-1)
    SP[5] = make_float2(1.f, 1.f);
    SM[5] = make_float2(1.f, 1.f);
#pragma unroll
    for (int j = 4; j >= 0; j--) {
        SP[j].x = SP[j + 1].x * (E[j + 1].x + 1.f);
        SP[j].y = SP[j + 1].y * (E[j + 1].y + 1.f);
        SM[j].x = SM[j + 1].x * (E[j + 1].x - 1.f);
        SM[j].y = SM[j + 1].y * (E[j + 1].y - 1.f);
    }
    float PPx = 1.f, PPy = 1.f, PMx = 1.f, PMy = 1.f;   // prefix products
#pragma unroll
    for (int j = 0; j < 6; j++) {
        float Bx = PPx * SP[j].x, Ax = PMx * SM[j].x;
        float By = PPy * SP[j].y, Ay = PMy * SM[j].y;
        float2 o;
        o.x = lg2f_(fmaf(CLIP, Ax, Bx)) - lg2f_(fmaf(-CLIP, Ax, Bx));
        o.y = lg2f_(fmaf(CLIP, Ay, By)) - lg2f_(fmaf(-CLIP, Ay, By));
        dst[2 * j] = o;
        PPx *= (E[j].x + 1.f); PPy *= (E[j].y + 1.f);
        PMx *= (E[j].x - 1.f); PMy *= (E[j].y - 1.f);
    }
}

// --------------------------------- main --------------------------------------
extern __shared__ float4 s_dyn[];

__global__ void __launch_bounds__(THREADS, 2)
bp_kernel(const float* __restrict__ llr, float* __restrict__ out) {
    float4* s_c2v = s_dyn;                 // CSLOTS float4 (56 KB), padded stride 7
    float4* s_llr = s_dyn + CSLOTS;        // LW_SLOTS float4 (18 KB), raw llr, staged once
    const int tid = threadIdx.x;
    const long b0 = (long)blockIdx.x * 4;
    const float* llr0 = llr + b0 * NN;

    // stage raw llr (4 batch lanes per variable) - once
#pragma unroll
    for (int k = 0; k < NN / THREADS; k++) {
        int v = tid + k * THREADS;
        float4 L;
        L.x = llr0[v];
        L.y = llr0[NN + v];
        L.z = llr0[2 * NN + v];
        L.w = llr0[3 * NN + v];
        s_llr[lwslot(v)] = L;
    }
    // zero c2v (iteration 0 reads zeros; padding slots unused but zeroed too)
#pragma unroll
    for (int k = 0; k < CSLOTS / THREADS; k++)
        s_c2v[tid + k * THREADS] = make_float4(0.f, 0.f, 0.f, 0.f);

    // this thread's 6 llr-table slots (iteration-invariant)
    int vsl[6];
    {
        const unsigned short* p = g_vslot + tid * 6;
#pragma unroll
        for (int j = 0; j < 6; j++) vsl[j] = p[j];
    }
    __syncthreads();

    float2* s2 = (float2*)s_c2v;
    float2* dst = s2 + tid * (2 * CSTRIDE);

    for (int it = 0; it < NITERS; it++) {
        const uint4* meta = g_meta + it * EE + tid * 6;
        float4 E4[6];
#pragma unroll
        for (int j = 0; j < 6; j++) {
            uint4 m = meta[j];
            float4 A  = s_c2v[m.x & 0xFFFFu];
            float4 Bv = s_c2v[m.x >> 16];
            float4 L  = s_llr[vsl[j]];
            float W0 = __uint_as_float(m.y);
            float W1 = __uint_as_float(m.z);
            float LW = __uint_as_float(m.w);
            float ux = fmaf(A.x, W0, fmaf(Bv.x, W1, L.x * LW));
            float uy = fmaf(A.y, W0, fmaf(Bv.y, W1, L.y * LW));
            float uz = fmaf(A.z, W0, fmaf(Bv.z, W1, L.z * LW));
            float uw = fmaf(A.w, W0, fmaf(Bv.w, W1, L.w * LW));
            ux = fminf(UCLAMP, fmaxf(-UCLAMP, ux));
            uy = fminf(UCLAMP, fmaxf(-UCLAMP, uy));
            uz = fminf(UCLAMP, fmaxf(-UCLAMP, uz));
            uw = fminf(UCLAMP, fmaxf(-UCLAMP, uw));
            E4[j].x = ex2f_(ux);
            E4[j].y = ex2f_(uy);
            E4[j].z = ex2f_(uz);
            E4[j].w = ex2f_(uw);
        }
        __syncthreads();   // all reads of old c2v complete

        {
            float2 E[6];
#pragma unroll
            for (int j = 0; j < 6; j++) E[j] = make_float2(E4[j].x, E4[j].y);
            check_pair(E, dst);          // writes .xy halves of slots
        }
        {
            float2 E[6];
#pragma unroll
            for (int j = 0; j < 6; j++) E[j] = make_float2(E4[j].z, E4[j].w);
            check_pair(E, dst + 1);      // writes .zw halves
        }
        __syncthreads();   // stores visible before next iteration's gathers
    }

    // final marginalization for variable v = tid (outputs are vars 0..511)
    uint2 fi = g_finidx[tid];
    float4 fw = g_finw[tid];
    float4 A  = s_c2v[fi.x & 0xFFFFu];
    float4 Bv = s_c2v[fi.x >> 16];
    float4 C  = s_c2v[fi.y];
    float4 L  = s_llr[lwslot(tid)];
    float4 o;
    o.x = fmaf(A.x, fw.x, fmaf(Bv.x, fw.y, fmaf(C.x, fw.z, L.x * fw.w)));
    o.y = fmaf(A.y, fw.x, fmaf(Bv.y, fw.y, fmaf(C.y, fw.z, L.y * fw.w)));
    o.z = fmaf(A.z, fw.x, fmaf(Bv.z, fw.y, fmaf(C.z, fw.z, L.z * fw.w)));
    o.w = fmaf(A.w, fw.x, fmaf(Bv.w, fw.y, fmaf(C.w, fw.z, L.w * fw.w)));
    out[(b0 + 0) * MM + tid] = rcpf_(1.0f + ex2f_(-o.x * LOG2E));
    out[(b0 + 1) * MM + tid] = rcpf_(1.0f + ex2f_(-o.y * LOG2E));
    out[(b0 + 2) * MM + tid] = rcpf_(1.0f + ex2f_(-o.z * LOG2E));
    out[(b0 + 3) * MM + tid] = rcpf_(1.0f + ex2f_(-o.w * LOG2E));
}

// ------------------------------ launch ---------------------------------------
extern "C" void kernel_launch(void* const* d_in, const int* in_sizes, int n_in,
                              void* d_out, int out_size) {
    const float* llr       = (const float*)d_in[0];
    const float* w_iter    = (const float*)d_in[1];
    const float* llr_iter  = (const float*)d_in[2];
    const float* w_final   = (const float*)d_in[3];
    const float* llr_final = (const float*)d_in[4];
    const int*   v_sum     = (const int*)d_in[5];
    // d_in[6] = c_prod_idx: redundant (check r owns edges 6r..6r+5 contiguously)
    const int*   edge_var  = (const int*)d_in[7];
    const int*   fin_idx   = (const int*)d_in[8];

    int B = in_sizes[0] / NN;                 // 8192
    size_t smem = (size_t)(CSLOTS + LW_SLOTS) * sizeof(float4);   // 74 KB

    cudaFuncSetAttribute(bp_kernel, cudaFuncAttributeMaxDynamicSharedMemorySize, (int)smem);

    prep_kernel<<<(NITERS * EE + 255) / 256, 256>>>(w_iter, llr_iter, w_final, llr_final,
                                                    v_sum, edge_var, fin_idx);
    bp_kernel<<<B / 4, THREADS, smem>>>(llr, (float*)d_out);
}